// round 9
// baseline (speedup 1.0000x reference)
#include <cuda_runtime.h>
#include <cstdint>
#include <cstddef>

#define VOCAB   50000
#define EMB     256
#define HID     512
#define NBATCH  256
#define T       512
#define NB      512
#define KTOT    768            // EMB + HID
#define GB_H    32
#define GB_B    4
#define NBLOCKS (GB_H * GB_B)  // 128
#define HS      16             // hid units per block -> 64 gate rows
#define BS      128            // batch rows per block
#define KSPLIT  2
#define KHALF   (KTOT / KSPLIT) // 384
#define KC      16             // K chunk per buffer slot
#define NCHUNK  (KHALF / KC)   // 24
#define THREADS 512
#define NWARP   16
#define RPW     16             // batch rows per warp
#define ROWF    KC             // floats per row per chunk = 16
#define BUFW    (RPW * ROWF)   // 256 floats per (warp,buffer)

// SMEM: weights 49152 floats (192KB) + staging/exchange 8192 floats (32KB) = 229376 B
#define WS_FLOATS   (HS * KTOT * 4)
#define INS_FLOATS  (NWARP * 2 * BUFW)
#define SMEM_BYTES  ((WS_FLOATS + INS_FLOATS) * 4)

__device__ float     g_h[2][NB * HID];
__device__ unsigned  g_cnt;
__device__ unsigned  g_gen;

__device__ __forceinline__ float2 unpack2(unsigned long long v) {
    float lo, hi;
    asm("mov.b64 {%0, %1}, %2;" : "=f"(lo), "=f"(hi) : "l"(v));
    return make_float2(lo, hi);
}
__device__ __forceinline__ float hadd2(unsigned long long v) {
    float2 f = unpack2(v);
    return f.x + f.y;
}
__device__ __forceinline__ void ffma2(unsigned long long& acc,
                                      unsigned long long a, unsigned long long b) {
    asm("fma.rn.f32x2 %0, %1, %2, %0;" : "+l"(acc) : "l"(a), "l"(b));
}
__device__ __forceinline__ void cp16_ca(void* dst, const void* src) {
    unsigned d = (unsigned)__cvta_generic_to_shared(dst);
    asm volatile("cp.async.ca.shared.global [%0], [%1], 16;" :: "r"(d), "l"(src));
}
__device__ __forceinline__ void cp16_cg(void* dst, const void* src) {
    unsigned d = (unsigned)__cvta_generic_to_shared(dst);
    asm volatile("cp.async.cg.shared.global [%0], [%1], 16;" :: "r"(d), "l"(src));
}
__device__ __forceinline__ float sigf(float x) {
    return __fdividef(1.0f, 1.0f + __expf(-x));
}
__device__ __forceinline__ float tanhx(float x) {
    return __fmaf_rn(2.0f, sigf(2.0f * x), -1.0f);
}

__device__ __forceinline__ void grid_sync() {
    __syncthreads();
    if (threadIdx.x == 0) {
        volatile unsigned* genp = &g_gen;
        unsigned g = *genp;
        __threadfence();
        if (atomicAdd(&g_cnt, 1u) == NBLOCKS - 1) {
            g_cnt = 0;
            __threadfence();
            *genp = g + 1;
        } else {
            while (*genp == g) { __nanosleep(40); }
        }
    }
    __syncthreads();
}

__global__ void __launch_bounds__(THREADS, 1)
lstm_twin_kernel(const int* __restrict__ in1, const int* __restrict__ in2,
                 const float* __restrict__ emb, const float* __restrict__ Wih,
                 const float* __restrict__ Whh, const float* __restrict__ bih,
                 const float* __restrict__ bhh, const float* __restrict__ Wfc,
                 const float* __restrict__ bfc, float* __restrict__ out)
{
    extern __shared__ float smem[];
    float* Ws  = smem;
    float* ins = smem + WS_FLOATS;

    const int tid = threadIdx.x;
    const int bid = blockIdx.x;
    const int hg  = bid & (GB_H - 1);
    const int bg  = bid >> 5;
    const int w   = tid >> 5;            // warp 0..15
    const int lid = tid & 31;
    const int ks  = tid >> 8;            // k-split half 0/1
    const int wr  = w & 7;               // row-block within half
    const int tbw = (tid >> 4) & 1;      // row parity within warp
    const int tj  = tid & 15;            // hid unit within tile
    const int jglob = hg * HS + tj;
    const int nbase = bg * BS;
    const int nbw   = nbase + wr * RPW;  // warp's first batch row
    const int kbase = ks * KHALF;
    const int warpbase = w * 2 * BUFW;

    // ---- weight tile -> SMEM, k-pair layout, NO swizzle ----
    // cell ci = (kp*2 + qq)*16 + tj  (16B each):
    //   { W[2qq+0][2kp], W[2qq+0][2kp+1], W[2qq+1][2kp], W[2qq+1][2kp+1] }
    for (int f = tid; f < WS_FLOATS; f += THREADS) {
        const int ci  = f >> 2;
        const int e   = f & 3;
        const int tjr = ci & 15;
        const int qq  = (ci >> 4) & 1;
        const int kp  = ci >> 5;
        const int q   = 2 * qq + (e >> 1);
        const int k   = 2 * kp + (e & 1);
        const int G   = q * HID + hg * HS + tjr;
        Ws[f] = (k < EMB) ? Wih[G * EMB + k] : Whh[G * HID + (k - EMB)];
    }

    // bias per gate (scalars, used by ks==0 combine)
    const float4 biasv = make_float4(
        bih[0 * HID + jglob] + bhh[0 * HID + jglob],
        bih[1 * HID + jglob] + bhh[1 * HID + jglob],
        bih[2 * HID + jglob] + bhh[2 * HID + jglob],
        bih[3 * HID + jglob] + bhh[3 * HID + jglob]);

    // zero h buffer 0
    {
        float* hz = &g_h[0][0];
        int base = (bid * THREADS + tid) * 4;
#pragma unroll
        for (int i = 0; i < 4; i++) hz[base + i] = 0.0f;
    }
    grid_sync();

    // ---- warp-private staging: 64 cells (16B) per chunk, 2 per lane ----
    const int sc  = lid & 3;              // cell column 0..3
    const int scf = sc * 4;               // float offset within row-chunk
    const int sr0 = lid >> 2;             // rows 0..7
    const int sr1 = sr0 + 8;              // rows 8..15
    const int d0  = sr0 * ROWF + ((sc ^ (sr0 & 3)) << 2);
    const int d1  = sr1 * ROWF + ((sc ^ (sr1 & 3)) << 2);
    const int gr0 = nbw + sr0;
    const int gr1 = nbw + sr1;

    const int* tokarr = (bg < 2) ? in1 : in2;
    const int  rowb   = (nbase & (NBATCH - 1)) + wr * RPW;
    const int* tp0 = tokarr + (size_t)(rowb + sr0) * T;
    const int* tp1 = tokarr + (size_t)(rowb + sr1) * T;

    int cur0 = __ldg(tp0);
    int cur1 = __ldg(tp1);

    float c[8];
#pragma unroll
    for (int b = 0; b < 8; b++) c[b] = 0.0f;

#pragma unroll 1
    for (int t = 0; t < T; t++) {
        const float* hread  = &g_h[t & 1][0];
        float*       hwrite = &g_h[(t + 1) & 1][0];

        const float* e0 = emb + (size_t)cur0 * EMB + scf;
        const float* e1 = emb + (size_t)cur1 * EMB + scf;
        const float* h0 = hread + (size_t)gr0 * HID + scf - EMB;
        const float* h1 = hread + (size_t)gr1 * HID + scf - EMB;

        // stage chunks 0 and 1
#pragma unroll
        for (int cc = 0; cc < 2; cc++) {
            const int kabs = kbase + cc * KC;
            float* dst = ins + warpbase + (cc & 1) * BUFW;
            if (kabs < EMB) {
                cp16_ca(dst + d0, e0 + kabs);
                cp16_ca(dst + d1, e1 + kabs);
            } else {
                cp16_cg(dst + d0, h0 + kabs);
                cp16_cg(dst + d1, h1 + kabs);
            }
            asm volatile("cp.async.commit_group;");
        }

        const int tn = (t + 1 < T) ? t + 1 : t;
        int nxt0 = __ldg(tp0 + tn);
        int nxt1 = __ldg(tp1 + tn);

        // acc[b][q]: f32x2, lanes = (even-k sum, odd-k sum) for gate q
        unsigned long long acc[8][4];
#pragma unroll
        for (int b = 0; b < 8; b++)
#pragma unroll
            for (int q = 0; q < 4; q++) acc[b][q] = 0ull;

#pragma unroll 1
        for (int cch = 0; cch < NCHUNK; cch++) {
            if (cch == NCHUNK - 1) {
                asm volatile("cp.async.wait_group 0;");
            } else {
                asm volatile("cp.async.wait_group 1;");
            }

            const float* xb = ins + warpbase + (cch & 1) * BUFW;
            const int kpb = (kbase + cch * KC) >> 1;   // first k-pair of chunk
#pragma unroll
            for (int kk = 0; kk < KC / 4; kk++) {
                const int kp = kpb + kk * 2;
                const ulonglong2* Wc = (const ulonglong2*)Ws;
                ulonglong2 wA0 = Wc[(kp * 2 + 0) * 16 + tj];   // gates01, kpair kp
                ulonglong2 wB0 = Wc[(kp * 2 + 1) * 16 + tj];   // gates23, kpair kp
                ulonglong2 wA1 = Wc[(kp * 2 + 2) * 16 + tj];   // gates01, kpair kp+1
                ulonglong2 wB1 = Wc[(kp * 2 + 3) * 16 + tj];   // gates23, kpair kp+1
#pragma unroll
                for (int b = 0; b < 8; b++) {
                    const int r = 2 * b + tbw;
                    ulonglong2 x = *(const ulonglong2*)(xb + r * ROWF + ((kk ^ (r & 3)) << 2));
                    ffma2(acc[b][0], x.x, wA0.x);
                    ffma2(acc[b][1], x.x, wA0.y);
                    ffma2(acc[b][2], x.x, wB0.x);
                    ffma2(acc[b][3], x.x, wB0.y);
                    ffma2(acc[b][0], x.y, wA1.x);
                    ffma2(acc[b][1], x.y, wA1.y);
                    ffma2(acc[b][2], x.y, wB1.x);
                    ffma2(acc[b][3], x.y, wB1.y);
                }
            }

            if (cch + 2 < NCHUNK) {
                const int kabs = kbase + (cch + 2) * KC;
                float* dst = ins + warpbase + (cch & 1) * BUFW;
                if (kabs < EMB) {
                    cp16_ca(dst + d0, e0 + kabs);
                    cp16_ca(dst + d1, e1 + kabs);
                } else {
                    cp16_cg(dst + d0, h0 + kabs);
                    cp16_cg(dst + d1, h1 + kabs);
                }
                asm volatile("cp.async.commit_group;");
            }
        }

        // ---- cross-half reduction (scalar gates) + pointwise ----
        __syncthreads();
        if (ks) {
            const int col = tid & 255;
#pragma unroll
            for (int b = 0; b < 8; b++) {
                *(float4*)(ins + b * 1024 + col * 4) = make_float4(
                    hadd2(acc[b][0]), hadd2(acc[b][1]),
                    hadd2(acc[b][2]), hadd2(acc[b][3]));
            }
        }
        __syncthreads();
        if (!ks) {
#pragma unroll
            for (int b = 0; b < 8; b++) {
                float4 p = *(const float4*)(ins + b * 1024 + tid * 4);
                float gi = hadd2(acc[b][0]) + p.x + biasv.x;
                float gf = hadd2(acc[b][1]) + p.y + biasv.y;
                float gc = hadd2(acc[b][2]) + p.z + biasv.z;
                float go = hadd2(acc[b][3]) + p.w + biasv.w;
                float ig = sigf(gi);
                float fg = sigf(gf);
                float gg = tanhx(gc);
                float og = sigf(go);
                c[b] = fg * c[b] + ig * gg;
                float hv = og * tanhx(c[b]);
                hwrite[(size_t)(nbw + 2 * b + tbw) * HID + jglob] = hv;
            }
        }

        cur0 = nxt0;
        cur1 = nxt1;
        grid_sync();
    }

    // epilogue: h = h1*h2 -> FC(2) -> softmax
    if (bid == 0 && tid < NBATCH) {
        const int n = tid;
        const float* h1 = &g_h[0][(size_t)n * HID];
        const float* h2 = &g_h[0][(size_t)(n + NBATCH) * HID];
        float l0 = bfc[0], l1 = bfc[1];
#pragma unroll 4
        for (int j = 0; j < HID; j++) {
            float hp = __ldcg(&h1[j]) * __ldcg(&h2[j]);
            l0 = __fmaf_rn(hp, Wfc[j], l0);
            l1 = __fmaf_rn(hp, Wfc[HID + j], l1);
        }
        float m  = fmaxf(l0, l1);
        float e0 = __expf(l0 - m);
        float e1 = __expf(l1 - m);
        float s  = __fdividef(1.0f, e0 + e1);
        out[n * 2 + 0] = e0 * s;
        out[n * 2 + 1] = e1 * s;
    }
}

extern "C" void kernel_launch(void* const* d_in, const int* in_sizes, int n_in,
                              void* d_out, int out_size)
{
    (void)in_sizes; (void)n_in; (void)out_size;
    const int*   in1 = (const int*)d_in[0];
    const int*   in2 = (const int*)d_in[1];
    const float* emb = (const float*)d_in[2];
    const float* Wih = (const float*)d_in[3];
    const float* Whh = (const float*)d_in[4];
    const float* bih = (const float*)d_in[5];
    const float* bhh = (const float*)d_in[6];
    const float* Wfc = (const float*)d_in[7];
    const float* bfc = (const float*)d_in[8];
    float* out = (float*)d_out;

    cudaFuncSetAttribute(lstm_twin_kernel,
                         cudaFuncAttributeMaxDynamicSharedMemorySize, SMEM_BYTES);
    lstm_twin_kernel<<<NBLOCKS, THREADS, SMEM_BYTES>>>(
        in1, in2, emb, Wih, Whh, bih, bhh, Wfc, bfc, out);
}

// round 11
// speedup vs baseline: 1.7260x; 1.7260x over previous
#include <cuda_runtime.h>
#include <cuda_bf16.h>
#include <cstdint>
#include <cstddef>

#define VOCAB   50000
#define EMB     256
#define HID     512
#define NBATCH  256
#define T       512
#define NB      512
#define NBLOCKS 128
#define THREADS 512

// SMEM byte layout
#define SM_BHI   0          // B_hi: 64 n-rows x 1536 B (768 k bf16), swizzled   (96 KB)
#define SM_BLO   98304      // B_lo                                              (96 KB)
#define SM_A     196608     // A staging: 2 halves x 2 bufs x 8 KB = 32 KB; reused as D-exchange
#define SM_BIAS  229376     // 64 floats
#define SMEM_BYTES 229632

__device__ __nv_bfloat16 g_ehi[(size_t)VOCAB * EMB];
__device__ __nv_bfloat16 g_elo[(size_t)VOCAB * EMB];
__device__ __nv_bfloat16 g_hhi[2][NB * HID];
__device__ __nv_bfloat16 g_hlo[2][NB * HID];
__device__ unsigned g_cnt, g_gen;

// ---------------- helpers ----------------
__device__ __forceinline__ uint32_t smem_u32(const void* p) {
    uint32_t a;
    asm("{ .reg .u64 t; cvta.to.shared.u64 t, %1; cvt.u32.u64 %0, t; }" : "=r"(a) : "l"(p));
    return a;
}
__device__ __forceinline__ void cp16_ca(uint32_t d, const void* s) {
    asm volatile("cp.async.ca.shared.global [%0], [%1], 16;" :: "r"(d), "l"(s));
}
__device__ __forceinline__ void cp16_cg(uint32_t d, const void* s) {
    asm volatile("cp.async.cg.shared.global [%0], [%1], 16;" :: "r"(d), "l"(s));
}
__device__ __forceinline__ void ldsm4(uint32_t& r0, uint32_t& r1, uint32_t& r2, uint32_t& r3,
                                      uint32_t addr) {
    asm volatile("ldmatrix.sync.aligned.m8n8.x4.shared.b16 {%0,%1,%2,%3}, [%4];"
                 : "=r"(r0), "=r"(r1), "=r"(r2), "=r"(r3) : "r"(addr));
}
__device__ __forceinline__ void mma16816(float* c, const uint32_t* a, const uint32_t* b) {
    asm volatile(
        "mma.sync.aligned.m16n8k16.row.col.f32.bf16.bf16.f32 "
        "{%0,%1,%2,%3},{%4,%5,%6,%7},{%8,%9},{%0,%1,%2,%3};"
        : "+f"(c[0]), "+f"(c[1]), "+f"(c[2]), "+f"(c[3])
        : "r"(a[0]), "r"(a[1]), "r"(a[2]), "r"(a[3]), "r"(b[0]), "r"(b[1]));
}
__device__ __forceinline__ float sigf(float x) {
    return __fdividef(1.0f, 1.0f + __expf(-x));
}
__device__ __forceinline__ float tanhx(float x) {
    return __fmaf_rn(2.0f, sigf(2.0f * x), -1.0f);
}
__device__ __forceinline__ void grid_sync() {
    __syncthreads();
    if (threadIdx.x == 0) {
        volatile unsigned* genp = &g_gen;
        unsigned g = *genp;
        __threadfence();
        if (atomicAdd(&g_cnt, 1u) == NBLOCKS - 1) {
            g_cnt = 0;
            __threadfence();
            *genp = g + 1;
        } else {
            while (*genp == g) { __nanosleep(40); }
        }
    }
    __syncthreads();
}

// ---------------- prep: split emb into bf16 hi/lo, zero h buf 0 ----------------
__global__ void prep_kernel(const float* __restrict__ emb) {
    const size_t stride = (size_t)gridDim.x * blockDim.x;
    size_t i = (size_t)blockIdx.x * blockDim.x + threadIdx.x;
    const size_t total = (size_t)VOCAB * EMB;
    for (size_t p = i; p < total; p += stride) {
        float v = emb[p];
        __nv_bfloat16 h = __float2bfloat16(v);
        g_ehi[p] = h;
        g_elo[p] = __float2bfloat16(v - __bfloat162float(h));
    }
    const __nv_bfloat16 z = __float2bfloat16(0.0f);
    for (size_t p = i; p < (size_t)NB * HID; p += stride) {
        g_hhi[0][p] = z;
        g_hlo[0][p] = z;
    }
}

// ---------------- persistent twin-LSTM on mma.sync (HMMA bf16 split) ----------------
__global__ void __launch_bounds__(THREADS, 1)
lstm_mma_kernel(const int* __restrict__ in1, const int* __restrict__ in2,
                const float* __restrict__ Wih, const float* __restrict__ Whh,
                const float* __restrict__ bih, const float* __restrict__ bhh,
                const float* __restrict__ Wfc, const float* __restrict__ bfc,
                float* __restrict__ out)
{
    extern __shared__ char smem[];
    const uint32_t sb = smem_u32(smem);
    const int tid  = threadIdx.x;
    const int bid  = blockIdx.x;
    const int hg   = bid & 31;        // 16-hid-unit slice
    const int bg   = bid >> 5;        // 128-batch-row group
    const int nbase = bg * 128;
    const int wid  = tid >> 5;
    const int lane = tid & 31;
    const int ks   = wid >> 3;        // k-half: 0 -> k[0,384), 1 -> k[384,768)
    const int w8   = wid & 7;
    const int m0   = (w8 >> 1) * 32;  // warp m-tile base
    const int n0   = (w8 & 1) * 32;   // warp n-tile base

    // ---- build resident B image (hi+lo), rows [n][k], swizzled 16B cells ----
    for (int f = tid; f < 64 * 768; f += THREADS) {
        const int n = f / 768;
        const int k = f - n * 768;
        const int q = n >> 4, j = n & 15;
        const int G = q * HID + hg * 16 + j;
        const float wv = (k < EMB) ? Wih[G * EMB + k] : Whh[G * HID + (k - EMB)];
        const __nv_bfloat16 whv = __float2bfloat16(wv);
        const __nv_bfloat16 wlv = __float2bfloat16(wv - __bfloat162float(whv));
        const int off = n * 1536 + (((k >> 3) ^ (n & 7)) << 4) + (k & 7) * 2;
        *(__nv_bfloat16*)(smem + SM_BHI + off) = whv;
        *(__nv_bfloat16*)(smem + SM_BLO + off) = wlv;
    }
    if (tid < 64) {
        const int q = tid >> 4, j = tid & 15;
        const int G = q * HID + hg * 16 + j;
        *(float*)(smem + SM_BIAS + tid * 4) = bih[G] + bhh[G];
    }
    __syncthreads();

    // ---- per-thread staging map (256 threads per k-half) ----
    const int th      = tid & 255;
    const int sm_row  = th >> 1;          // batch row 0..127
    const int cellbit = th & 1;           // which 16B cell of the k16 chunk
    const int grow    = nbase + sm_row;
    const int* tokp   = (grow < NBATCH) ? in1 + (size_t)grow * T
                                        : in2 + (size_t)(grow - NBATCH) * T;
    const uint32_t adst = sb + SM_A + (uint32_t)(ks * 16384 + cellbit * 2048 + sm_row * 16);

    // ---- ldmatrix A offsets (within a buffer; layout [kcell][m][16B]) ----
    uint32_t aoff[2];
#pragma unroll
    for (int mi = 0; mi < 2; mi++)
        aoff[mi] = (uint32_t)((lane >> 4) * 2048 + (m0 + mi * 16 + (lane & 15)) * 16);

    // ---- ldmatrix B row bases + swizzle terms ----
    const int kbit = (lane >> 3) & 1;
    const int nB0 = n0 + (lane & 7) + ((lane >> 4) << 3);   // x4 #0 covers n0..n0+15
    const int nB1 = nB0 + 16;                               // x4 #1 covers n0+16..n0+31
    const uint32_t bhi0 = sb + SM_BHI + (uint32_t)(nB0 * 1536);
    const uint32_t bhi1 = sb + SM_BHI + (uint32_t)(nB1 * 1536);
    const uint32_t blo0 = sb + SM_BLO + (uint32_t)(nB0 * 1536);
    const uint32_t blo1 = sb + SM_BLO + (uint32_t)(nB1 * 1536);
    const uint32_t q30 = (uint32_t)((kbit ^ (nB0 & 7)) << 4);
    const uint32_t q31 = (uint32_t)((kbit ^ (nB1 & 7)) << 4);

    // pointwise mapping
    const int pm  = tid & 127;
    const int pj0 = (tid >> 7) * 4;

    float cst[4];
#pragma unroll
    for (int i = 0; i < 4; i++) cst[i] = 0.0f;

    float* Dex = (float*)(smem + SM_A);
    const float* bias = (const float*)(smem + SM_BIAS);

#pragma unroll 1
    for (int t = 0; t < T; t++) {
        const int hb = t & 1;
        const int tok = __ldg(tokp + t);
        const __nv_bfloat16* hh = g_hhi[hb];
        const __nv_bfloat16* hl = g_hlo[hb];

        // stage one k16 chunk (hi 4KB + lo 4KB) for this thread's half
        auto stage_chunk = [&](int c) {
            const int k0 = ks * 384 + c * 16 + cellbit * 8;
            const uint32_t dst = adst + (uint32_t)((c & 1) * 8192);
            if (k0 < EMB) {
                cp16_ca(dst,        g_ehi + (size_t)tok * EMB + k0);
                cp16_ca(dst + 4096, g_elo + (size_t)tok * EMB + k0);
            } else {
                const size_t off = (size_t)grow * HID + (k0 - EMB);
                cp16_cg(dst,        hh + off);
                cp16_cg(dst + 4096, hl + off);
            }
            asm volatile("cp.async.commit_group;");
        };

        stage_chunk(0);
        stage_chunk(1);

        float acc[2][4][4];
#pragma unroll
        for (int mi = 0; mi < 2; mi++)
#pragma unroll
            for (int ni = 0; ni < 4; ni++)
#pragma unroll
                for (int e = 0; e < 4; e++) acc[mi][ni][e] = 0.0f;

#pragma unroll 1
        for (int c = 0; c < 24; c++) {
            if (c < 23) { asm volatile("cp.async.wait_group 1;"); }
            else        { asm volatile("cp.async.wait_group 0;"); }
            asm volatile("bar.sync %0, %1;" :: "r"(1 + ks), "r"(256) : "memory");

            const uint32_t abase = sb + SM_A + (uint32_t)(ks * 16384 + (c & 1) * 8192);

            uint32_t ah[2][4], al[2][4];
#pragma unroll
            for (int mi = 0; mi < 2; mi++) {
                ldsm4(ah[mi][0], ah[mi][1], ah[mi][2], ah[mi][3], abase + aoff[mi]);
                ldsm4(al[mi][0], al[mi][1], al[mi][2], al[mi][3], abase + 4096 + aoff[mi]);
            }

            const uint32_t kcb = (uint32_t)((ks * 48 + 2 * c) << 4);
            uint32_t bh[4][2], bl[4][2];
            ldsm4(bh[0][0], bh[0][1], bh[1][0], bh[1][1], bhi0 + (kcb ^ q30));
            ldsm4(bh[2][0], bh[2][1], bh[3][0], bh[3][1], bhi1 + (kcb ^ q31));
            ldsm4(bl[0][0], bl[0][1], bl[1][0], bl[1][1], blo0 + (kcb ^ q30));
            ldsm4(bl[2][0], bl[2][1], bl[3][0], bl[3][1], blo1 + (kcb ^ q31));

#pragma unroll
            for (int mi = 0; mi < 2; mi++)
#pragma unroll
                for (int ni = 0; ni < 4; ni++) {
                    mma16816(acc[mi][ni], ah[mi], bh[ni]);   // hi*hi
                    mma16816(acc[mi][ni], ah[mi], bl[ni]);   // hi*lo
                    mma16816(acc[mi][ni], al[mi], bh[ni]);   // lo*hi
                }

            asm volatile("bar.sync %0, %1;" :: "r"(1 + ks), "r"(256) : "memory");
            if (c + 2 < 24) stage_chunk(c + 2);
        }

        // ---- combine halves in SMEM (reuse staging region as D-exchange) ----
        __syncthreads();
        if (ks == 0) {
#pragma unroll
            for (int mi = 0; mi < 2; mi++)
#pragma unroll
                for (int ni = 0; ni < 4; ni++) {
                    const int r  = m0 + 16 * mi + (lane >> 2);
                    const int p  = (n0 + 8 * ni + 2 * (lane & 3)) >> 1;
                    *(float2*)((char*)Dex + r * 256 + (((p) ^ ((r & 7) << 2)) << 3)) =
                        make_float2(acc[mi][ni][0], acc[mi][ni][1]);
                    const int r2 = r + 8;
                    *(float2*)((char*)Dex + r2 * 256 + (((p) ^ ((r2 & 7) << 2)) << 3)) =
                        make_float2(acc[mi][ni][2], acc[mi][ni][3]);
                }
        }
        __syncthreads();
        if (ks == 1) {
#pragma unroll
            for (int mi = 0; mi < 2; mi++)
#pragma unroll
                for (int ni = 0; ni < 4; ni++) {
                    const int r  = m0 + 16 * mi + (lane >> 2);
                    const int p  = (n0 + 8 * ni + 2 * (lane & 3)) >> 1;
                    float2* p1 = (float2*)((char*)Dex + r * 256 + (((p) ^ ((r & 7) << 2)) << 3));
                    float2 v1 = *p1;
                    v1.x += acc[mi][ni][0]; v1.y += acc[mi][ni][1];
                    *p1 = v1;
                    const int r2 = r + 8;
                    float2* p2 = (float2*)((char*)Dex + r2 * 256 + (((p) ^ ((r2 & 7) << 2)) << 3));
                    float2 v2 = *p2;
                    v2.x += acc[mi][ni][2]; v2.y += acc[mi][ni][3];
                    *p2 = v2;
                }
        }
        __syncthreads();

        // ---- pointwise LSTM cell: thread handles (pm, pj0..pj0+3) ----
        {
            unsigned long long packh = 0ull, packl = 0ull;
#pragma unroll
            for (int jj = 0; jj < 4; jj++) {
                const int j = pj0 + jj;
                float gv[4];
#pragma unroll
                for (int q = 0; q < 4; q++) {
                    const int n = q * 16 + j;
                    gv[q] = *(const float*)((const char*)Dex + pm * 256 +
                             (((n >> 1) ^ ((pm & 7) << 2)) << 3) + (n & 1) * 4)
                            + bias[n];
                }
                float ig = sigf(gv[0]);
                float fg = sigf(gv[1]);
                float gg = tanhx(gv[2]);
                float og = sigf(gv[3]);
                cst[jj] = fg * cst[jj] + ig * gg;
                float hv = og * tanhx(cst[jj]);
                __nv_bfloat16 hb16 = __float2bfloat16(hv);
                float hrem = hv - __bfloat162float(hb16);
                __nv_bfloat16 lb16 = __float2bfloat16(hrem);
                packh |= (unsigned long long)(*(unsigned short*)&hb16) << (16 * jj);
                packl |= (unsigned long long)(*(unsigned short*)&lb16) << (16 * jj);
            }
            const size_t hoff = (size_t)(nbase + pm) * HID + hg * 16 + pj0;
            *(unsigned long long*)(g_hhi[hb ^ 1] + hoff) = packh;
            *(unsigned long long*)(g_hlo[hb ^ 1] + hoff) = packl;
        }

        grid_sync();
    }

    // ---- final: h = h1*h2 -> FC(2) -> softmax (final h in buf 0) ----
    if (bid == 0 && tid < NBATCH) {
        const int n = tid;
        const __nv_bfloat16* a_h = g_hhi[0] + (size_t)n * HID;
        const __nv_bfloat16* a_l = g_hlo[0] + (size_t)n * HID;
        const __nv_bfloat16* b_h = g_hhi[0] + (size_t)(n + NBATCH) * HID;
        const __nv_bfloat16* b_l = g_hlo[0] + (size_t)(n + NBATCH) * HID;
        float l0 = bfc[0], l1 = bfc[1];
#pragma unroll 4
        for (int j = 0; j < HID; j++) {
            float h1 = __bfloat162float(a_h[j]) + __bfloat162float(a_l[j]);
            float h2 = __bfloat162float(b_h[j]) + __bfloat162float(b_l[j]);
            float hp = h1 * h2;
            l0 = __fmaf_rn(hp, Wfc[j], l0);
            l1 = __fmaf_rn(hp, Wfc[HID + j], l1);
        }
        float m  = fmaxf(l0, l1);
        float e0 = __expf(l0 - m);
        float e1 = __expf(l1 - m);
        float s  = __fdividef(1.0f, e0 + e1);
        out[n * 2 + 0] = e0 * s;
        out[n * 2 + 1] = e1 * s;
    }
}

extern "C" void kernel_launch(void* const* d_in, const int* in_sizes, int n_in,
                              void* d_out, int out_size)
{
    (void)in_sizes; (void)n_in; (void)out_size;
    const int*   in1 = (const int*)d_in[0];
    const int*   in2 = (const int*)d_in[1];
    const float* emb = (const float*)d_in[2];
    const float* Wih = (const float*)d_in[3];
    const float* Whh = (const float*)d_in[4];
    const float* bih = (const float*)d_in[5];
    const float* bhh = (const float*)d_in[6];
    const float* Wfc = (const float*)d_in[7];
    const float* bfc = (const float*)d_in[8];
    float* out = (float*)d_out;

    prep_kernel<<<2048, 256>>>(emb);

    cudaFuncSetAttribute(lstm_mma_kernel,
                         cudaFuncAttributeMaxDynamicSharedMemorySize, SMEM_BYTES);
    lstm_mma_kernel<<<NBLOCKS, THREADS, SMEM_BYTES>>>(
        in1, in2, Wih, Whh, bih, bhh, Wfc, bfc, out);
}